// round 14
// baseline (speedup 1.0000x reference)
#include <cuda_runtime.h>
#include <cuda_bf16.h>
#include <cuda_fp16.h>
#include <math.h>

#define N_MAX 100000
#define M_MAX 1600000
#define CH 128
#define KVOL 27
#define BN_EPS 1e-5f

// ---------------- scratch (device globals; no runtime allocation) ----------
__device__ float g_x  [(size_t)N_MAX * CH];
__device__ float g_q  [(size_t)N_MAX * CH];
__device__ __half g_vh[(size_t)N_MAX * CH];   // v in fp16
__device__ float g_acc[(size_t)N_MAX * CH];
__device__ float g_npe[KVOL * CH];
__device__ float g_s1[8];
__device__ float g_s2[2 * CH];
__device__ float g_bn1[6];       // sc0..2, shf0..2
__device__ int   g_cnt[N_MAX];
__device__ int   g_off[N_MAX];   // local-exclusive within 1024-chunk
__device__ int   g_cur[N_MAX];   // local-exclusive cursor
__device__ int   g_sorted[M_MAX];   // encoded key*32 + kern
__device__ int   g_bsum[128];
__device__ int   g_bbase[128];
// weight panels, transposed to [n][k] K-major, bf16 split hi/lo (3-term)
// index: 0=W3, 1=Wq, 2=Wv, 3=Wo
__device__ __nv_bfloat16 g_Whi[4][CH * CH];
__device__ __nv_bfloat16 g_Wlo[4][CH * CH];

// ---------------- stats for BN1 + weight prep + q-histogram (fused) --------
// grid MUST be 256 blocks x 256 threads (65536 = 4 * 128 * 128)
__global__ void __launch_bounds__(256) stats1_kernel(
        const float* __restrict__ points, const float* __restrict__ W1, int n,
        const float* __restrict__ W3, const float* __restrict__ Wq,
        const float* __restrict__ Wv, const float* __restrict__ Wo,
        const int* __restrict__ kq, int M) {
    int gid = blockIdx.x * 256 + threadIdx.x;      // 0..65535
    {
        int w = gid >> 14;
        int e = gid & 16383;
        int k = e >> 7, nn = e & 127;
        const float* Wsrc = (w == 0) ? W3 : (w == 1) ? Wq : (w == 2) ? Wv : Wo;
        float x = __ldg(&Wsrc[k * CH + nn]);
        __nv_bfloat16 hi = __float2bfloat16(x);
        __nv_bfloat16 lo = __float2bfloat16(x - __bfloat162float(hi));
        g_Whi[w][nn * CH + k] = hi;
        g_Wlo[w][nn * CH + k] = lo;
    }
    // fused histogram of q_idx
    for (int i = gid; i < M; i += 65536)
        atomicAdd(&g_cnt[__ldg(&kq[M + i])], 1);

    __shared__ float sh[6];
    if (threadIdx.x < 6) sh[threadIdx.x] = 0.f;
    __syncthreads();
    float w[9];
#pragma unroll
    for (int i = 0; i < 9; i++) w[i] = __ldg(&W1[i]);
    float s[3] = {0.f, 0.f, 0.f}, q[3] = {0.f, 0.f, 0.f};
    for (int i = gid; i < n; i += 65536) {
        float px = points[i * 3 + 0], py = points[i * 3 + 1], pz = points[i * 3 + 2];
#pragma unroll
        for (int j = 0; j < 3; j++) {
            float h = px * w[j] + py * w[3 + j] + pz * w[6 + j];
            s[j] += h; q[j] += h * h;
        }
    }
#pragma unroll
    for (int o = 16; o; o >>= 1) {
#pragma unroll
        for (int j = 0; j < 3; j++) {
            s[j] += __shfl_down_sync(0xFFFFFFFFu, s[j], o);
            q[j] += __shfl_down_sync(0xFFFFFFFFu, q[j], o);
        }
    }
    if ((threadIdx.x & 31) == 0) {
#pragma unroll
        for (int j = 0; j < 3; j++) {
            atomicAdd(&sh[j], s[j]);
            atomicAdd(&sh[3 + j], q[j]);
        }
    }
    __syncthreads();
    if (threadIdx.x < 6) atomicAdd(&g_s1[threadIdx.x], sh[threadIdx.x]);
}

// ---------------- BN2 stats only (h2 recomputed in gemm, never stored) -----
#define H2_PB 128
__global__ void __launch_bounds__(256) h2_kernel(
        const float* __restrict__ points, const float* __restrict__ W1,
        const float* __restrict__ g1, const float* __restrict__ b1,
        const float* __restrict__ W2, int n) {
    __shared__ float ssum[CH], ssq[CH];
    int tid = threadIdx.x;
    if (tid < CH) { ssum[tid] = 0.f; ssq[tid] = 0.f; }
    __syncthreads();

    float w1[9];
#pragma unroll
    for (int i = 0; i < 9; i++) w1[i] = __ldg(&W1[i]);
    float invn = 1.f / (float)n;
    float sc[3], shf[3];
#pragma unroll
    for (int j = 0; j < 3; j++) {
        float mu  = g_s1[j] * invn;
        float var = g_s1[3 + j] * invn - mu * mu;
        float rs  = rsqrtf(var + BN_EPS);
        float s   = rs * __ldg(&g1[j]);
        sc[j] = s; shf[j] = __ldg(&b1[j]) - mu * s;
    }
    if (blockIdx.x == 0 && tid < 3) {
        g_bn1[tid] = sc[tid];
        g_bn1[3 + tid] = shf[tid];
    }
    int lane = tid & 31, wid = tid >> 5;
    int c0 = lane * 4;
    float w2a[4], w2b[4], w2c[4];
#pragma unroll
    for (int i = 0; i < 4; i++) {
        w2a[i] = __ldg(&W2[0 * CH + c0 + i]);
        w2b[i] = __ldg(&W2[1 * CH + c0 + i]);
        w2c[i] = __ldg(&W2[2 * CH + c0 + i]);
    }
    float ls[4] = {0, 0, 0, 0}, lq[4] = {0, 0, 0, 0};
    int base = blockIdx.x * H2_PB;
    int nend = min(base + H2_PB, n);
    for (int p = base + wid; p < nend; p += 8) {
        float px = __ldg(&points[p * 3 + 0]);
        float py = __ldg(&points[p * 3 + 1]);
        float pz = __ldg(&points[p * 3 + 2]);
        float a[3];
#pragma unroll
        for (int j = 0; j < 3; j++) {
            float h = px * w1[j] + py * w1[3 + j] + pz * w1[6 + j];
            a[j] = fmaxf(h * sc[j] + shf[j], 0.f);
        }
#pragma unroll
        for (int i = 0; i < 4; i++) {
            float o = a[0] * w2a[i] + a[1] * w2b[i] + a[2] * w2c[i];
            ls[i] += o; lq[i] += o * o;
        }
    }
#pragma unroll
    for (int i = 0; i < 4; i++) {
        atomicAdd(&ssum[c0 + i], ls[i]);
        atomicAdd(&ssq[c0 + i], lq[i]);
    }
    __syncthreads();
    if (tid < CH) {
        atomicAdd(&g_s2[tid], ssum[tid]);
        atomicAdd(&g_s2[CH + tid], ssq[tid]);
    }
}

// ---------------- persistent tensor-core GEMM helpers ----------------------
#define SASTRIDE 136
#define BM 32
#define SB_ELEMS (128 * SASTRIDE)
#define ABUF_ELEMS (BM * SASTRIDE)
#define GEMM_GRID 296
#define QV_GRID 148
#define QV_BM 64
#define TC_SMEM_1 ((2 * SB_ELEMS + 4 * ABUF_ELEMS) * 2 + 256 * 4)
#define TC_SMEM_QV ((4 * SB_ELEMS + 8 * ABUF_ELEMS) * 2)

#define LDSM4(R0, R1, R2, R3, ADDR) \
    asm volatile("ldmatrix.sync.aligned.m8n8.x4.shared.b16 {%0,%1,%2,%3}, [%4];" \
        : "=r"(R0), "=r"(R1), "=r"(R2), "=r"(R3) : "r"(ADDR))

__device__ __forceinline__ void mma16816(float* c, const unsigned* a, const unsigned* b) {
    asm volatile(
        "mma.sync.aligned.m16n8k16.row.col.f32.bf16.bf16.f32 "
        "{%0,%1,%2,%3}, {%4,%5,%6,%7}, {%8,%9}, {%0,%1,%2,%3};"
        : "+f"(c[0]), "+f"(c[1]), "+f"(c[2]), "+f"(c[3])
        : "r"(a[0]), "r"(a[1]), "r"(a[2]), "r"(a[3]), "r"(b[0]), "r"(b[1]));
}

__device__ __forceinline__ void store_a_split(
        __nv_bfloat16* sAhi, __nv_bfloat16* sAlo, int r, int c, float4 a) {
    __nv_bfloat162 h0 = __floats2bfloat162_rn(a.x, a.y);
    __nv_bfloat162 h1 = __floats2bfloat162_rn(a.z, a.w);
    float2 h0f = __bfloat1622float2(h0);
    float2 h1f = __bfloat1622float2(h1);
    __nv_bfloat162 l0 = __floats2bfloat162_rn(a.x - h0f.x, a.y - h0f.y);
    __nv_bfloat162 l1 = __floats2bfloat162_rn(a.z - h1f.x, a.w - h1f.y);
    *(__nv_bfloat162*)&sAhi[r * SASTRIDE + c]     = h0;
    *(__nv_bfloat162*)&sAhi[r * SASTRIDE + c + 2] = h1;
    *(__nv_bfloat162*)&sAlo[r * SASTRIDE + c]     = l0;
    *(__nv_bfloat162*)&sAlo[r * SASTRIDE + c + 2] = l1;
}

// ---------------- single-weight persistent GEMM (3-term split) -------------
// MODE 0: C = A@W + bias
// MODE 1: A' = relu(bn2(relu(bn1(points@W1))@W2)); C = A'@W + bias + extra
template <int MODE>
__global__ void __launch_bounds__(256, 2) gemm_p(
        const float* __restrict__ A, const __nv_bfloat16* __restrict__ Bhi,
        const __nv_bfloat16* __restrict__ Blo, const float* __restrict__ bias,
        float* __restrict__ C, const float* __restrict__ extra,
        const float* __restrict__ gamma, const float* __restrict__ beta,
        const float* __restrict__ points, const float* __restrict__ W1,
        const float* __restrict__ W2, int nrows) {
    extern __shared__ char smraw[];
    __nv_bfloat16* sBhi = (__nv_bfloat16*)smraw;
    __nv_bfloat16* sBlo = sBhi + SB_ELEMS;
    __nv_bfloat16* sA   = sBlo + SB_ELEMS;
    float* s_sc = (float*)(sA + 4 * ABUF_ELEMS);
    float* s_sh = s_sc + CH;

    int tid = threadIdx.x;
#pragma unroll
    for (int i = 0; i < 8; i++) {
        int g = i * 256 + tid;
        int nn = g >> 4;
        int kk = (g & 15) * 8;
        *(uint4*)&sBhi[nn * SASTRIDE + kk] = __ldg((const uint4*)&Bhi[nn * CH + kk]);
        *(uint4*)&sBlo[nn * SASTRIDE + kk] = __ldg((const uint4*)&Blo[nn * CH + kk]);
    }
    if (MODE == 1 && tid < CH) {
        float invn = 1.f / (float)nrows;
        float mu  = g_s2[tid] * invn;
        float var = g_s2[CH + tid] * invn - mu * mu;
        float rs  = rsqrtf(var + BN_EPS);
        float s   = rs * __ldg(&gamma[tid]);
        s_sc[tid] = s; s_sh[tid] = __ldg(&beta[tid]) - mu * s;
    }
    __syncthreads();

    int rbase = tid >> 5;
    int c = (tid & 31) * 4;
    float w1[9], sc1[3], sh1[3];
    float4 w20, w21, w22, sc4, sh4;
    if (MODE == 1) {
#pragma unroll
        for (int i = 0; i < 9; i++) w1[i] = __ldg(&W1[i]);
#pragma unroll
        for (int j = 0; j < 3; j++) { sc1[j] = g_bn1[j]; sh1[j] = g_bn1[3 + j]; }
        w20 = __ldg((const float4*)&W2[0 * CH + c]);
        w21 = __ldg((const float4*)&W2[1 * CH + c]);
        w22 = __ldg((const float4*)&W2[2 * CH + c]);
        sc4 = *(const float4*)&s_sc[c];
        sh4 = *(const float4*)&s_sh[c];
    }

    int wid = tid >> 5, lane = tid & 31;
    int warp_m = (wid & 1) * 16;
    int warp_n = (wid >> 1) * 32;
    int rq = lane >> 2;
    int kq = (lane & 3) * 2;

    unsigned uA   = (unsigned)__cvta_generic_to_shared(sA);
    unsigned uBhi = (unsigned)__cvta_generic_to_shared(sBhi);
    unsigned uBlo = (unsigned)__cvta_generic_to_shared(sBlo);
    int arow = warp_m + (lane & 15);
    int acol = (lane >> 4) * 8;
    unsigned aOff = (unsigned)((arow * SASTRIDE + acol) * 2);
    int brow = warp_n + (lane & 7) + ((lane >> 4) & 1) * 8;
    int bcol = ((lane >> 3) & 1) * 8;
    unsigned bHi = uBhi + (unsigned)((brow * SASTRIDE + bcol) * 2);
    unsigned bLo = uBlo + (unsigned)((brow * SASTRIDE + bcol) * 2);
    const unsigned BROW16 = 16 * SASTRIDE * 2;
    const unsigned ABUF_B = 2 * ABUF_ELEMS * 2;
    const unsigned ALO_B  = ABUF_ELEMS * 2;

    int ntiles = (nrows + BM - 1) / BM;
    int t = blockIdx.x;

    float4 pref[4];
#define LOAD_PREF(TT)                                                         \
    {                                                                         \
        _Pragma("unroll")                                                     \
        for (int i = 0; i < 4; i++) {                                         \
            int row = (TT) * BM + i * 8 + rbase;                              \
            float4 a = make_float4(0.f, 0.f, 0.f, 0.f);                       \
            if (row < nrows) {                                                \
                if (MODE == 1) {                                              \
                    float px = __ldg(&points[row * 3 + 0]);                   \
                    float py = __ldg(&points[row * 3 + 1]);                   \
                    float pz = __ldg(&points[row * 3 + 2]);                   \
                    float t0 = fmaxf(fmaf(px * w1[0] + py * w1[3] + pz * w1[6], sc1[0], sh1[0]), 0.f); \
                    float t1 = fmaxf(fmaf(px * w1[1] + py * w1[4] + pz * w1[7], sc1[1], sh1[1]), 0.f); \
                    float t2 = fmaxf(fmaf(px * w1[2] + py * w1[5] + pz * w1[8], sc1[2], sh1[2]), 0.f); \
                    a.x = fmaxf(fmaf(t0 * w20.x + t1 * w21.x + t2 * w22.x, sc4.x, sh4.x), 0.f); \
                    a.y = fmaxf(fmaf(t0 * w20.y + t1 * w21.y + t2 * w22.y, sc4.y, sh4.y), 0.f); \
                    a.z = fmaxf(fmaf(t0 * w20.z + t1 * w21.z + t2 * w22.z, sc4.z, sh4.z), 0.f); \
                    a.w = fmaxf(fmaf(t0 * w20.w + t1 * w21.w + t2 * w22.w, sc4.w, sh4.w), 0.f); \
                } else {                                                      \
                    a = __ldg((const float4*)&A[(size_t)row * CH + c]);       \
                }                                                             \
            }                                                                 \
            pref[i] = a;                                                      \
        }                                                                     \
    }
    if (t < ntiles) LOAD_PREF(t);

    int it = 0;
    while (t < ntiles) {
        int buf = it & 1;
        __nv_bfloat16* sAhi = sA + buf * 2 * ABUF_ELEMS;
        __nv_bfloat16* sAlo = sAhi + ABUF_ELEMS;
#pragma unroll
        for (int i = 0; i < 4; i++)
            store_a_split(sAhi, sAlo, i * 8 + rbase, c, pref[i]);
        __syncthreads();

        int row_lo = t * BM + warp_m + rq;
        int row_hi = row_lo + 8;
        bool ok_lo = row_lo < nrows, ok_hi = row_hi < nrows;

        float2 ext[8];
        if (MODE == 1) {
#pragma unroll
            for (int nt = 0; nt < 4; nt++) {
                int col = warp_n + nt * 8 + kq;
                ext[nt]     = ok_lo ? __ldg((const float2*)&extra[(size_t)row_lo * CH + col])
                                    : make_float2(0.f, 0.f);
                ext[4 + nt] = ok_hi ? __ldg((const float2*)&extra[(size_t)row_hi * CH + col])
                                    : make_float2(0.f, 0.f);
            }
        }
        int tn = t + GEMM_GRID;
        if (tn < ntiles) LOAD_PREF(tn);

        unsigned aHi = uA + buf * ABUF_B + aOff;
        unsigned aLo = aHi + ALO_B;
        float acc[4][4];
#pragma unroll
        for (int nt = 0; nt < 4; nt++)
#pragma unroll
            for (int j = 0; j < 4; j++) acc[nt][j] = 0.f;
#pragma unroll
        for (int ks = 0; ks < 8; ks++) {
            unsigned ko = ks * 32;
            unsigned ah[4], al[4];
            LDSM4(ah[0], ah[1], ah[2], ah[3], aHi + ko);
            LDSM4(al[0], al[1], al[2], al[3], aLo + ko);
            unsigned bh[8], bl[8];
            LDSM4(bh[0], bh[1], bh[2], bh[3], bHi + ko);
            LDSM4(bh[4], bh[5], bh[6], bh[7], bHi + BROW16 + ko);
            LDSM4(bl[0], bl[1], bl[2], bl[3], bLo + ko);
            LDSM4(bl[4], bl[5], bl[6], bl[7], bLo + BROW16 + ko);
#pragma unroll
            for (int nt = 0; nt < 4; nt++) {
                mma16816(acc[nt], ah, bh + 2 * nt);
                mma16816(acc[nt], ah, bl + 2 * nt);
                mma16816(acc[nt], al, bh + 2 * nt);
            }
        }

#pragma unroll
        for (int nt = 0; nt < 4; nt++) {
            int col = warp_n + nt * 8 + kq;
            float2 bs = *(const float2*)&bias[col];
            acc[nt][0] += bs.x; acc[nt][1] += bs.y;
            acc[nt][2] += bs.x; acc[nt][3] += bs.y;
            if (MODE == 1) {
                acc[nt][0] += ext[nt].x;     acc[nt][1] += ext[nt].y;
                acc[nt][2] += ext[4 + nt].x; acc[nt][3] += ext[4 + nt].y;
            }
            if (ok_lo)
                *(float2*)&C[(size_t)row_lo * CH + col] =
                    make_float2(acc[nt][0], acc[nt][1]);
            if (ok_hi)
                *(float2*)&C[(size_t)row_hi * CH + col] =
                    make_float2(acc[nt][2], acc[nt][3]);
        }
        t = tn; ++it;
    }
#undef LOAD_PREF
}

// ---------------- merged q+v persistent GEMM, 64-row pair tiles ------------
// B fragments loaded once per k-step and reused across both 32-row subtiles.
__global__ void __launch_bounds__(256, 1) gemm_qv(
        const float* __restrict__ A,
        const __nv_bfloat16* __restrict__ Bqh, const __nv_bfloat16* __restrict__ Bql,
        const __nv_bfloat16* __restrict__ Bvh, const __nv_bfloat16* __restrict__ Bvl,
        const float* __restrict__ bq, const float* __restrict__ bv,
        float* __restrict__ Cq, __half* __restrict__ Cv, int nrows) {
    extern __shared__ char smraw[];
    __nv_bfloat16* sBqh = (__nv_bfloat16*)smraw;
    __nv_bfloat16* sBql = sBqh + SB_ELEMS;
    __nv_bfloat16* sBvh = sBql + SB_ELEMS;
    __nv_bfloat16* sBvl = sBvh + SB_ELEMS;
    __nv_bfloat16* sA   = sBvl + SB_ELEMS;   // [buf][sub][hi|lo]

    int tid = threadIdx.x;
#pragma unroll
    for (int i = 0; i < 8; i++) {
        int g = i * 256 + tid;
        int nn = g >> 4;
        int kk = (g & 15) * 8;
        *(uint4*)&sBqh[nn * SASTRIDE + kk] = __ldg((const uint4*)&Bqh[nn * CH + kk]);
        *(uint4*)&sBql[nn * SASTRIDE + kk] = __ldg((const uint4*)&Bql[nn * CH + kk]);
        *(uint4*)&sBvh[nn * SASTRIDE + kk] = __ldg((const uint4*)&Bvh[nn * CH + kk]);
        *(uint4*)&sBvl[nn * SASTRIDE + kk] = __ldg((const uint4*)&Bvl[nn * CH + kk]);
    }
    __syncthreads();

    int rbase = tid >> 5;
    int c = (tid & 31) * 4;
    int wid = tid >> 5, lane = tid & 31;
    int warp_m = (wid & 1) * 16;
    int warp_n = (wid >> 1) * 32;
    int rq = lane >> 2;
    int kq = (lane & 3) * 2;

    unsigned uA   = (unsigned)__cvta_generic_to_shared(sA);
    unsigned uBqh = (unsigned)__cvta_generic_to_shared(sBqh);
    unsigned uBql = (unsigned)__cvta_generic_to_shared(sBql);
    unsigned uBvh = (unsigned)__cvta_generic_to_shared(sBvh);
    unsigned uBvl = (unsigned)__cvta_generic_to_shared(sBvl);
    int arow = warp_m + (lane & 15);
    int acol = (lane >> 4) * 8;
    unsigned aOff = (unsigned)((arow * SASTRIDE + acol) * 2);
    int brow = warp_n + (lane & 7) + ((lane >> 4) & 1) * 8;
    int bcol = ((lane >> 3) & 1) * 8;
    unsigned bQh = uBqh + (unsigned)((brow * SASTRIDE + bcol) * 2);
    unsigned bQl = uBql + (unsigned)((brow * SASTRIDE + bcol) * 2);
    unsigned bVh = uBvh + (unsigned)((brow * SASTRIDE + bcol) * 2);
    unsigned bVl = uBvl + (unsigned)((brow * SASTRIDE + bcol) * 2);
    const unsigned BROW16 = 16 * SASTRIDE * 2;
    const unsigned SUB_B  = ABUF_ELEMS * 2;         // bytes per hi or lo plane
    const unsigned BUF_B  = 4 * ABUF_ELEMS * 2;     // bytes per double-buffer slot

    int ntiles = (nrows + QV_BM - 1) / QV_BM;
    int t = blockIdx.x;

    float4 pref[8];
#define LOAD_PREF_QV(TT)                                                      \
    {                                                                         \
        _Pragma("unroll")                                                     \
        for (int s = 0; s < 2; s++) {                                         \
            _Pragma("unroll")                                                 \
            for (int i = 0; i < 4; i++) {                                     \
                int row = (TT) * QV_BM + s * 32 + i * 8 + rbase;              \
                pref[s * 4 + i] = (row < nrows)                               \
                    ? __ldg((const float4*)&A[(size_t)row * CH + c])          \
                    : make_float4(0.f, 0.f, 0.f, 0.f);                        \
            }                                                                 \
        }                                                                     \
    }
    if (t < ntiles) LOAD_PREF_QV(t);

    int it = 0;
    while (t < ntiles) {
        int buf = it & 1;
        __nv_bfloat16* base = sA + buf * 4 * ABUF_ELEMS;
#pragma unroll
        for (int s = 0; s < 2; s++) {
            __nv_bfloat16* sAhi = base + s * 2 * ABUF_ELEMS;
            __nv_bfloat16* sAlo = sAhi + ABUF_ELEMS;
#pragma unroll
            for (int i = 0; i < 4; i++)
                store_a_split(sAhi, sAlo, i * 8 + rbase, c, pref[s * 4 + i]);
        }
        __syncthreads();

        int tn = t + QV_GRID;
        if (tn < ntiles) LOAD_PREF_QV(tn);

        float accq[2][4][4], accv[2][4][4];
#pragma unroll
        for (int s = 0; s < 2; s++)
#pragma unroll
            for (int nt = 0; nt < 4; nt++)
#pragma unroll
                for (int j = 0; j < 4; j++) { accq[s][nt][j] = 0.f; accv[s][nt][j] = 0.f; }

        unsigned a0 = uA + buf * BUF_B + aOff;           // sub0 hi
#pragma unroll
        for (int ks = 0; ks < 8; ks++) {
            unsigned ko = ks * 32;
            // B fragments once per ks (shared across both subtiles)
            unsigned qh[8], ql[8], vh[8], vl[8];
            LDSM4(qh[0], qh[1], qh[2], qh[3], bQh + ko);
            LDSM4(qh[4], qh[5], qh[6], qh[7], bQh + BROW16 + ko);
            LDSM4(ql[0], ql[1], ql[2], ql[3], bQl + ko);
            LDSM4(ql[4], ql[5], ql[6], ql[7], bQl + BROW16 + ko);
            LDSM4(vh[0], vh[1], vh[2], vh[3], bVh + ko);
            LDSM4(vh[4], vh[5], vh[6], vh[7], bVh + BROW16 + ko);
            LDSM4(vl[0], vl[1], vl[2], vl[3], bVl + ko);
            LDSM4(vl[4], vl[5], vl[6], vl[7], bVl + BROW16 + ko);
#pragma unroll
            for (int s = 0; s < 2; s++) {
                unsigned aHi = a0 + s * 2 * SUB_B;
                unsigned ah[4], al[4];
                LDSM4(ah[0], ah[1], ah[2], ah[3], aHi + ko);
                LDSM4(al[0], al[1], al[2], al[3], aHi + SUB_B + ko);
#pragma unroll
                for (int nt = 0; nt < 4; nt++) {
                    mma16816(accq[s][nt], ah, qh + 2 * nt);
                    mma16816(accq[s][nt], ah, ql + 2 * nt);
                    mma16816(accq[s][nt], al, qh + 2 * nt);
                    mma16816(accv[s][nt], ah, vh + 2 * nt);
                    mma16816(accv[s][nt], ah, vl + 2 * nt);
                    mma16816(accv[s][nt], al, vh + 2 * nt);
                }
            }
        }

        // ---- epilogue per subtile ----
#pragma unroll
        for (int s = 0; s < 2; s++) {
            int row_lo = t * QV_BM + s * 32 + warp_m + rq;
            int row_hi = row_lo + 8;
            bool ok_lo = row_lo < nrows, ok_hi = row_hi < nrows;
#pragma unroll
            for (int nt = 0; nt < 4; nt++) {
                int col = warp_n + nt * 8 + kq;
                float2 bs = *(const float2*)&bq[col];
                accq[s][nt][0] += bs.x; accq[s][nt][1] += bs.y;
                accq[s][nt][2] += bs.x; accq[s][nt][3] += bs.y;
            }
#pragma unroll
            for (int hp = 0; hp < 2; hp++) {
                int n0 = hp * 2, n1 = n0 + 1;
                float s0 = accq[s][n0][0] * accq[s][n0][0] + accq[s][n0][1] * accq[s][n0][1]
                         + accq[s][n1][0] * accq[s][n1][0] + accq[s][n1][1] * accq[s][n1][1];
                float s1 = accq[s][n0][2] * accq[s][n0][2] + accq[s][n0][3] * accq[s][n0][3]
                         + accq[s][n1][2] * accq[s][n1][2] + accq[s][n1][3] * accq[s][n1][3];
                s0 += __shfl_xor_sync(0xFFFFFFFFu, s0, 1);
                s0 += __shfl_xor_sync(0xFFFFFFFFu, s0, 2);
                s1 += __shfl_xor_sync(0xFFFFFFFFu, s1, 1);
                s1 += __shfl_xor_sync(0xFFFFFFFFu, s1, 2);
                float i0 = 1.f / fmaxf(sqrtf(s0), 1e-12f);
                float i1 = 1.f / fmaxf(sqrtf(s1), 1e-12f);
                accq[s][n0][0] *= i0; accq[s][n0][1] *= i0;
                accq[s][n1][0] *= i0; accq[s][n1][1] *= i0;
                accq[s][n0][2] *= i1; accq[s][n0][3] *= i1;
                accq[s][n1][2] *= i1; accq[s][n1][3] *= i1;
            }
#pragma unroll
            for (int nt = 0; nt < 4; nt++) {
                int col = warp_n + nt * 8 + kq;
                float2 bs = *(const float2*)&bv[col];
                accv[s][nt][0] += bs.x; accv[s][nt][1] += bs.y;
                accv[s][nt][2] += bs.x; accv[s][nt][3] += bs.y;
                if (ok_lo) {
                    *(float2*)&Cq[(size_t)row_lo * CH + col] =
                        make_float2(accq[s][nt][0], accq[s][nt][1]);
                    *(__half2*)&Cv[(size_t)row_lo * CH + col] =
                        __floats2half2_rn(accv[s][nt][0], accv[s][nt][1]);
                }
                if (ok_hi) {
                    *(float2*)&Cq[(size_t)row_hi * CH + col] =
                        make_float2(accq[s][nt][2], accq[s][nt][3]);
                    *(__half2*)&Cv[(size_t)row_hi * CH + col] =
                        __floats2half2_rn(accv[s][nt][2], accv[s][nt][3]);
                }
            }
        }
        t = tn; ++it;
    }
#undef LOAD_PREF_QV
}

// ---------------- 2-stage exclusive scan (scan3 folded into consumers) -----
#define SC_CHUNK 1024
__global__ void __launch_bounds__(SC_CHUNK) scan1_kernel(int n) {
    __shared__ int sm[SC_CHUNK];
    int t = threadIdx.x;
    int i = blockIdx.x * SC_CHUNK + t;
    int v = (i < n) ? g_cnt[i] : 0;
    sm[t] = v;
    __syncthreads();
#pragma unroll
    for (int o = 1; o < SC_CHUNK; o <<= 1) {
        int x = (t >= o) ? sm[t - o] : 0;
        __syncthreads();
        sm[t] += x;
        __syncthreads();
    }
    if (i < n) {
        int loc = sm[t] - v;
        g_off[i] = loc;
        g_cur[i] = loc;
    }
    if (t == SC_CHUNK - 1) g_bsum[blockIdx.x] = sm[t];
}

__global__ void __launch_bounds__(256) scan2_kernel(int nb, const float* __restrict__ pos_enc) {
    __shared__ int sm[128];
    int t = threadIdx.x;
    if (t < 128) {
        int v = (t < nb) ? g_bsum[t] : 0;
        sm[t] = v;
        __syncthreads();
#pragma unroll
        for (int o = 1; o < 128; o <<= 1) {
            int x = (t >= o) ? sm[t - o] : 0;
            __syncthreads();
            sm[t] += x;
            __syncthreads();
        }
        if (t < nb) g_bbase[t] = sm[t] - v;
    } else {
        __syncthreads();
#pragma unroll
        for (int o = 1; o < 128; o <<= 1) { __syncthreads(); __syncthreads(); }
    }
    for (int g = t; g < KVOL * 8; g += 256) {
        const float* src = pos_enc + g * 16;
        float v[16]; float s = 0.f;
#pragma unroll
        for (int i = 0; i < 16; i++) { v[i] = src[i]; s += v[i] * v[i]; }
        float inv = 1.f / fmaxf(sqrtf(s), 1e-12f);
#pragma unroll
        for (int i = 0; i < 16; i++) g_npe[g * 16 + i] = v[i] * inv;
    }
}

__global__ void __launch_bounds__(256) place_kernel(const int* __restrict__ kq, int M) {
    int i = blockIdx.x * blockDim.x + threadIdx.x;
    if (i < M) {
        int q = __ldg(&kq[M + i]);
        int pos = atomicAdd(&g_cur[q], 1) + g_bbase[q >> 10];
        int kk = __ldg(&kq[i]);
        int key = kk / KVOL;
        int kern = kk - key * KVOL;
        g_sorted[pos] = (key << 5) | kern;
    }
}

// ---------------- persistent segment gather: warp per query ----------------
#define GATHER_BLOCKS 592
__global__ void __launch_bounds__(256) gather_kernel(int n) {
    __shared__ float s_npe[KVOL * CH];
    for (int i = threadIdx.x; i < KVOL * CH / 4; i += 256)
        ((float4*)s_npe)[i] = ((const float4*)g_npe)[i];
    __syncthreads();

    int lane = threadIdx.x & 31;
    int c4 = lane * 4;
    int wid0 = (blockIdx.x * 256 + threadIdx.x) >> 5;
    const int nwarps = GATHER_BLOCKS * 8;

    for (int gw = wid0; gw < n; gw += nwarps) {
        int beg = __ldg(&g_off[gw]) + __ldg(&g_bbase[gw >> 10]);
        int cnt = __ldg(&g_cnt[gw]);
        float4 qv = __ldcs((const float4*)&g_q[(size_t)gw * CH + c4]);
        float4 acc = make_float4(0.f, 0.f, 0.f, 0.f);

        int i = 0;
        for (; i + 8 <= cnt; i += 8) {
            int e[8];
#pragma unroll
            for (int j = 0; j < 8; j++) e[j] = __ldg(&g_sorted[beg + i + j]);
            uint2 vh[8];
#pragma unroll
            for (int j = 0; j < 8; j++)
                vh[j] = __ldg((const uint2*)&g_vh[(size_t)(e[j] >> 5) * CH + c4]);
            float s[8];
#pragma unroll
            for (int j = 0; j < 8; j++) {
                float4 p = *(const float4*)&s_npe[(e[j] & 31) * CH + c4];
                float t = qv.x * p.x + qv.y * p.y + qv.z * p.z + qv.w * p.w;
                t += __shfl_xor_sync(0xFFFFFFFFu, t, 1);
                t += __shfl_xor_sync(0xFFFFFFFFu, t, 2);
                s[j] = t;
            }
#pragma unroll
            for (int j = 0; j < 8; j++) {
                float2 v0 = __half22float2(*(const __half2*)&vh[j].x);
                float2 v1 = __half22float2(*(const __half2*)&vh[j].y);
                acc.x = fmaf(s[j], v0.x, acc.x);
                acc.y = fmaf(s[j], v0.y, acc.y);
                acc.z = fmaf(s[j], v1.x, acc.z);
                acc.w = fmaf(s[j], v1.y, acc.w);
            }
        }
        if (i + 4 <= cnt) {
            int e[4];
#pragma unroll
            for (int j = 0; j < 4; j++) e[j] = __ldg(&g_sorted[beg + i + j]);
            uint2 vh[4];
#pragma unroll
            for (int j = 0; j < 4; j++)
                vh[j] = __ldg((const uint2*)&g_vh[(size_t)(e[j] >> 5) * CH + c4]);
#pragma unroll
            for (int j = 0; j < 4; j++) {
                float4 p = *(const float4*)&s_npe[(e[j] & 31) * CH + c4];
                float t = qv.x * p.x + qv.y * p.y + qv.z * p.z + qv.w * p.w;
                t += __shfl_xor_sync(0xFFFFFFFFu, t, 1);
                t += __shfl_xor_sync(0xFFFFFFFFu, t, 2);
                float2 v0 = __half22float2(*(const __half2*)&vh[j].x);
                float2 v1 = __half22float2(*(const __half2*)&vh[j].y);
                acc.x = fmaf(t, v0.x, acc.x);
                acc.y = fmaf(t, v0.y, acc.y);
                acc.z = fmaf(t, v1.x, acc.z);
                acc.w = fmaf(t, v1.y, acc.w);
            }
            i += 4;
        }
        for (; i < cnt; i++) {
            int e = __ldg(&g_sorted[beg + i]);
            uint2 vh = __ldg((const uint2*)&g_vh[(size_t)(e >> 5) * CH + c4]);
            float4 p = *(const float4*)&s_npe[(e & 31) * CH + c4];
            float t = qv.x * p.x + qv.y * p.y + qv.z * p.z + qv.w * p.w;
            t += __shfl_xor_sync(0xFFFFFFFFu, t, 1);
            t += __shfl_xor_sync(0xFFFFFFFFu, t, 2);
            float2 v0 = __half22float2(*(const __half2*)&vh.x);
            float2 v1 = __half22float2(*(const __half2*)&vh.y);
            acc.x = fmaf(t, v0.x, acc.x);
            acc.y = fmaf(t, v0.y, acc.y);
            acc.z = fmaf(t, v1.x, acc.z);
            acc.w = fmaf(t, v1.y, acc.w);
        }
        *(float4*)&g_acc[(size_t)gw * CH + c4] = acc;
    }
}

// ---------------- host launch ----------------------------------------------
extern "C" void kernel_launch(void* const* d_in, const int* in_sizes, int n_in,
                              void* d_out, int out_size) {
    const float* feats   = (const float*)d_in[0];
    const float* points  = (const float*)d_in[1];
    const int*   kq      = (const int*)d_in[2];
    const float* W1 = (const float*)d_in[3];
    const float* g1 = (const float*)d_in[4];
    const float* b1 = (const float*)d_in[5];
    const float* W2 = (const float*)d_in[6];
    const float* g2 = (const float*)d_in[7];
    const float* b2 = (const float*)d_in[8];
    const float* W3 = (const float*)d_in[9];
    const float* b3 = (const float*)d_in[10];
    const float* Wq = (const float*)d_in[11];
    const float* bq = (const float*)d_in[12];
    const float* Wv = (const float*)d_in[13];
    const float* bv = (const float*)d_in[14];
    const float* pos_enc = (const float*)d_in[15];
    const float* Wo = (const float*)d_in[16];
    const float* bo = (const float*)d_in[17];

    int N = in_sizes[0] / CH;
    int M = in_sizes[2] / 2;

    cudaFuncSetAttribute((const void*)gemm_p<0>,
                         cudaFuncAttributeMaxDynamicSharedMemorySize, TC_SMEM_1);
    cudaFuncSetAttribute((const void*)gemm_p<1>,
                         cudaFuncAttributeMaxDynamicSharedMemorySize, TC_SMEM_1);
    cudaFuncSetAttribute((const void*)gemm_qv,
                         cudaFuncAttributeMaxDynamicSharedMemorySize, TC_SMEM_QV);

    float* xp; float* qp; float* ap; __half* vhp;
    __nv_bfloat16* whi; __nv_bfloat16* wlo;
    { void* t; cudaGetSymbolAddress(&t, g_x);   xp  = (float*)t; }
    { void* t; cudaGetSymbolAddress(&t, g_q);   qp  = (float*)t; }
    { void* t; cudaGetSymbolAddress(&t, g_vh);  vhp = (__half*)t; }
    { void* t; cudaGetSymbolAddress(&t, g_acc); ap  = (float*)t; }
    { void* t; cudaGetSymbolAddress(&t, g_Whi); whi = (__nv_bfloat16*)t; }
    { void* t; cudaGetSymbolAddress(&t, g_Wlo); wlo = (__nv_bfloat16*)t; }
    void* cntp = nullptr; void* s1p = nullptr; void* s2p = nullptr;
    cudaGetSymbolAddress(&cntp, g_cnt);
    cudaGetSymbolAddress(&s1p, g_s1);
    cudaGetSymbolAddress(&s2p, g_s2);
    cudaMemsetAsync(cntp, 0, (size_t)N * sizeof(int), 0);
    cudaMemsetAsync(s1p, 0, 8 * sizeof(float), 0);
    cudaMemsetAsync(s2p, 0, 2 * CH * sizeof(float), 0);

    int nsb = (N + SC_CHUNK - 1) / SC_CHUNK;

    stats1_kernel<<<256, 256>>>(points, W1, N, W3, Wq, Wv, Wo, kq, M);
    h2_kernel<<<(N + H2_PB - 1) / H2_PB, 256>>>(points, W1, g1, b1, W2, N);

    // x = relu(bn2(h2(points))) @ W3 + b3 + feats
    gemm_p<1><<<GEMM_GRID, 256, TC_SMEM_1>>>(nullptr, whi + 0 * CH * CH, wlo + 0 * CH * CH,
                                             b3, xp, feats, g2, b2, points, W1, W2, N);
    // q (l2norm, fp32) and v (fp16) in one pass over x, 64-row pair tiles
    gemm_qv<<<QV_GRID, 256, TC_SMEM_QV>>>(xp,
                                          whi + 1 * CH * CH, wlo + 1 * CH * CH,
                                          whi + 2 * CH * CH, wlo + 2 * CH * CH,
                                          bq, bv, qp, vhp, N);

    // counting sort
    scan1_kernel<<<nsb, SC_CHUNK>>>(N);
    scan2_kernel<<<1, 256>>>(nsb, pos_enc);
    place_kernel<<<(M + 255) / 256, 256>>>(kq, M);

    // attention: persistent segment gather
    gather_kernel<<<GATHER_BLOCKS, 256>>>(N);

    // out = acc @ Wo + bo
    gemm_p<0><<<GEMM_GRID, 256, TC_SMEM_1>>>(ap, whi + 3 * CH * CH, wlo + 3 * CH * CH,
                                             bo, (float*)d_out, nullptr, nullptr, nullptr,
                                             nullptr, nullptr, nullptr, N);
}

// round 15
// speedup vs baseline: 1.0158x; 1.0158x over previous
#include <cuda_runtime.h>
#include <cuda_bf16.h>
#include <cuda_fp16.h>
#include <math.h>

#define N_MAX 100000
#define M_MAX 1600000
#define CH 128
#define KVOL 27
#define BN_EPS 1e-5f

// ---------------- scratch (device globals; no runtime allocation) ----------
__device__ float g_x  [(size_t)N_MAX * CH];
__device__ float g_q  [(size_t)N_MAX * CH];
__device__ __half g_vh[(size_t)N_MAX * CH];   // v in fp16
__device__ float g_acc[(size_t)N_MAX * CH];
__device__ float g_npe[KVOL * CH];
__device__ float g_s1[8];
__device__ float g_s2[2 * CH];
__device__ float g_bn1[6];       // sc0..2, shf0..2
__device__ int   g_cnt[N_MAX];
__device__ int   g_off[N_MAX];   // local-exclusive within 1024-chunk
__device__ int   g_cur[N_MAX];   // local-exclusive cursor
__device__ int   g_sorted[M_MAX];   // encoded key*32 + kern
__device__ int   g_bsum[128];
__device__ int   g_bbase[128];
// weight panels, transposed to [n][k] K-major, bf16 split hi/lo (3-term)
// index: 0=W3, 1=Wq, 2=Wv, 3=Wo
__device__ __nv_bfloat16 g_Whi[4][CH * CH];
__device__ __nv_bfloat16 g_Wlo[4][CH * CH];

// ---------------- stats for BN1 + weight prep + q-histogram (fused) --------
// grid MUST be 256 blocks x 256 threads (65536 = 4 * 128 * 128)
__global__ void __launch_bounds__(256) stats1_kernel(
        const float* __restrict__ points, const float* __restrict__ W1, int n,
        const float* __restrict__ W3, const float* __restrict__ Wq,
        const float* __restrict__ Wv, const float* __restrict__ Wo,
        const int* __restrict__ kq, int M) {
    int gid = blockIdx.x * 256 + threadIdx.x;      // 0..65535
    {
        int w = gid >> 14;
        int e = gid & 16383;
        int k = e >> 7, nn = e & 127;
        const float* Wsrc = (w == 0) ? W3 : (w == 1) ? Wq : (w == 2) ? Wv : Wo;
        float x = __ldg(&Wsrc[k * CH + nn]);
        __nv_bfloat16 hi = __float2bfloat16(x);
        __nv_bfloat16 lo = __float2bfloat16(x - __bfloat162float(hi));
        g_Whi[w][nn * CH + k] = hi;
        g_Wlo[w][nn * CH + k] = lo;
    }
    // fused histogram of q_idx
    for (int i = gid; i < M; i += 65536)
        atomicAdd(&g_cnt[__ldg(&kq[M + i])], 1);

    __shared__ float sh[6];
    if (threadIdx.x < 6) sh[threadIdx.x] = 0.f;
    __syncthreads();
    float w[9];
#pragma unroll
    for (int i = 0; i < 9; i++) w[i] = __ldg(&W1[i]);
    float s[3] = {0.f, 0.f, 0.f}, q[3] = {0.f, 0.f, 0.f};
    for (int i = gid; i < n; i += 65536) {
        float px = points[i * 3 + 0], py = points[i * 3 + 1], pz = points[i * 3 + 2];
#pragma unroll
        for (int j = 0; j < 3; j++) {
            float h = px * w[j] + py * w[3 + j] + pz * w[6 + j];
            s[j] += h; q[j] += h * h;
        }
    }
#pragma unroll
    for (int o = 16; o; o >>= 1) {
#pragma unroll
        for (int j = 0; j < 3; j++) {
            s[j] += __shfl_down_sync(0xFFFFFFFFu, s[j], o);
            q[j] += __shfl_down_sync(0xFFFFFFFFu, q[j], o);
        }
    }
    if ((threadIdx.x & 31) == 0) {
#pragma unroll
        for (int j = 0; j < 3; j++) {
            atomicAdd(&sh[j], s[j]);
            atomicAdd(&sh[3 + j], q[j]);
        }
    }
    __syncthreads();
    if (threadIdx.x < 6) atomicAdd(&g_s1[threadIdx.x], sh[threadIdx.x]);
}

// ---------------- BN2 stats only (h2 recomputed in gemm, never stored) -----
#define H2_PB 128
__global__ void __launch_bounds__(256) h2_kernel(
        const float* __restrict__ points, const float* __restrict__ W1,
        const float* __restrict__ g1, const float* __restrict__ b1,
        const float* __restrict__ W2, int n) {
    __shared__ float ssum[CH], ssq[CH];
    int tid = threadIdx.x;
    if (tid < CH) { ssum[tid] = 0.f; ssq[tid] = 0.f; }
    __syncthreads();

    float w1[9];
#pragma unroll
    for (int i = 0; i < 9; i++) w1[i] = __ldg(&W1[i]);
    float invn = 1.f / (float)n;
    float sc[3], shf[3];
#pragma unroll
    for (int j = 0; j < 3; j++) {
        float mu  = g_s1[j] * invn;
        float var = g_s1[3 + j] * invn - mu * mu;
        float rs  = rsqrtf(var + BN_EPS);
        float s   = rs * __ldg(&g1[j]);
        sc[j] = s; shf[j] = __ldg(&b1[j]) - mu * s;
    }
    if (blockIdx.x == 0 && tid < 3) {
        g_bn1[tid] = sc[tid];
        g_bn1[3 + tid] = shf[tid];
    }
    int lane = tid & 31, wid = tid >> 5;
    int c0 = lane * 4;
    float w2a[4], w2b[4], w2c[4];
#pragma unroll
    for (int i = 0; i < 4; i++) {
        w2a[i] = __ldg(&W2[0 * CH + c0 + i]);
        w2b[i] = __ldg(&W2[1 * CH + c0 + i]);
        w2c[i] = __ldg(&W2[2 * CH + c0 + i]);
    }
    float ls[4] = {0, 0, 0, 0}, lq[4] = {0, 0, 0, 0};
    int base = blockIdx.x * H2_PB;
    int nend = min(base + H2_PB, n);
    for (int p = base + wid; p < nend; p += 8) {
        float px = __ldg(&points[p * 3 + 0]);
        float py = __ldg(&points[p * 3 + 1]);
        float pz = __ldg(&points[p * 3 + 2]);
        float a[3];
#pragma unroll
        for (int j = 0; j < 3; j++) {
            float h = px * w1[j] + py * w1[3 + j] + pz * w1[6 + j];
            a[j] = fmaxf(h * sc[j] + shf[j], 0.f);
        }
#pragma unroll
        for (int i = 0; i < 4; i++) {
            float o = a[0] * w2a[i] + a[1] * w2b[i] + a[2] * w2c[i];
            ls[i] += o; lq[i] += o * o;
        }
    }
#pragma unroll
    for (int i = 0; i < 4; i++) {
        atomicAdd(&ssum[c0 + i], ls[i]);
        atomicAdd(&ssq[c0 + i], lq[i]);
    }
    __syncthreads();
    if (tid < CH) {
        atomicAdd(&g_s2[tid], ssum[tid]);
        atomicAdd(&g_s2[CH + tid], ssq[tid]);
    }
}

// ---------------- persistent tensor-core GEMM helpers ----------------------
#define SASTRIDE 136
#define BM 32
#define SB_ELEMS (128 * SASTRIDE)
#define ABUF_ELEMS (BM * SASTRIDE)
#define GEMM_GRID 296
#define QV_GRID 148
#define QV_BM 64
#define QV_THREADS 512
#define ABUF64 (QV_BM * SASTRIDE)
#define TC_SMEM_1 ((2 * SB_ELEMS + 4 * ABUF_ELEMS) * 2 + 256 * 4)
#define TC_SMEM_QV ((4 * SB_ELEMS + 4 * ABUF64) * 2)

#define LDSM4(R0, R1, R2, R3, ADDR) \
    asm volatile("ldmatrix.sync.aligned.m8n8.x4.shared.b16 {%0,%1,%2,%3}, [%4];" \
        : "=r"(R0), "=r"(R1), "=r"(R2), "=r"(R3) : "r"(ADDR))

__device__ __forceinline__ void mma16816(float* c, const unsigned* a, const unsigned* b) {
    asm volatile(
        "mma.sync.aligned.m16n8k16.row.col.f32.bf16.bf16.f32 "
        "{%0,%1,%2,%3}, {%4,%5,%6,%7}, {%8,%9}, {%0,%1,%2,%3};"
        : "+f"(c[0]), "+f"(c[1]), "+f"(c[2]), "+f"(c[3])
        : "r"(a[0]), "r"(a[1]), "r"(a[2]), "r"(a[3]), "r"(b[0]), "r"(b[1]));
}

__device__ __forceinline__ void store_a_split(
        __nv_bfloat16* sAhi, __nv_bfloat16* sAlo, int r, int c, float4 a) {
    __nv_bfloat162 h0 = __floats2bfloat162_rn(a.x, a.y);
    __nv_bfloat162 h1 = __floats2bfloat162_rn(a.z, a.w);
    float2 h0f = __bfloat1622float2(h0);
    float2 h1f = __bfloat1622float2(h1);
    __nv_bfloat162 l0 = __floats2bfloat162_rn(a.x - h0f.x, a.y - h0f.y);
    __nv_bfloat162 l1 = __floats2bfloat162_rn(a.z - h1f.x, a.w - h1f.y);
    *(__nv_bfloat162*)&sAhi[r * SASTRIDE + c]     = h0;
    *(__nv_bfloat162*)&sAhi[r * SASTRIDE + c + 2] = h1;
    *(__nv_bfloat162*)&sAlo[r * SASTRIDE + c]     = l0;
    *(__nv_bfloat162*)&sAlo[r * SASTRIDE + c + 2] = l1;
}

// ---------------- single-weight persistent GEMM (3-term split) -------------
// MODE 0: C = A@W + bias
// MODE 1: A' = relu(bn2(relu(bn1(points@W1))@W2)); C = A'@W + bias + extra
template <int MODE>
__global__ void __launch_bounds__(256, 2) gemm_p(
        const float* __restrict__ A, const __nv_bfloat16* __restrict__ Bhi,
        const __nv_bfloat16* __restrict__ Blo, const float* __restrict__ bias,
        float* __restrict__ C, const float* __restrict__ extra,
        const float* __restrict__ gamma, const float* __restrict__ beta,
        const float* __restrict__ points, const float* __restrict__ W1,
        const float* __restrict__ W2, int nrows) {
    extern __shared__ char smraw[];
    __nv_bfloat16* sBhi = (__nv_bfloat16*)smraw;
    __nv_bfloat16* sBlo = sBhi + SB_ELEMS;
    __nv_bfloat16* sA   = sBlo + SB_ELEMS;
    float* s_sc = (float*)(sA + 4 * ABUF_ELEMS);
    float* s_sh = s_sc + CH;

    int tid = threadIdx.x;
#pragma unroll
    for (int i = 0; i < 8; i++) {
        int g = i * 256 + tid;
        int nn = g >> 4;
        int kk = (g & 15) * 8;
        *(uint4*)&sBhi[nn * SASTRIDE + kk] = __ldg((const uint4*)&Bhi[nn * CH + kk]);
        *(uint4*)&sBlo[nn * SASTRIDE + kk] = __ldg((const uint4*)&Blo[nn * CH + kk]);
    }
    if (MODE == 1 && tid < CH) {
        float invn = 1.f / (float)nrows;
        float mu  = g_s2[tid] * invn;
        float var = g_s2[CH + tid] * invn - mu * mu;
        float rs  = rsqrtf(var + BN_EPS);
        float s   = rs * __ldg(&gamma[tid]);
        s_sc[tid] = s; s_sh[tid] = __ldg(&beta[tid]) - mu * s;
    }
    __syncthreads();

    int rbase = tid >> 5;
    int c = (tid & 31) * 4;
    float w1[9], sc1[3], sh1[3];
    float4 w20, w21, w22, sc4, sh4;
    if (MODE == 1) {
#pragma unroll
        for (int i = 0; i < 9; i++) w1[i] = __ldg(&W1[i]);
#pragma unroll
        for (int j = 0; j < 3; j++) { sc1[j] = g_bn1[j]; sh1[j] = g_bn1[3 + j]; }
        w20 = __ldg((const float4*)&W2[0 * CH + c]);
        w21 = __ldg((const float4*)&W2[1 * CH + c]);
        w22 = __ldg((const float4*)&W2[2 * CH + c]);
        sc4 = *(const float4*)&s_sc[c];
        sh4 = *(const float4*)&s_sh[c];
    }

    int wid = tid >> 5, lane = tid & 31;
    int warp_m = (wid & 1) * 16;
    int warp_n = (wid >> 1) * 32;
    int rq = lane >> 2;
    int kq = (lane & 3) * 2;

    unsigned uA   = (unsigned)__cvta_generic_to_shared(sA);
    unsigned uBhi = (unsigned)__cvta_generic_to_shared(sBhi);
    unsigned uBlo = (unsigned)__cvta_generic_to_shared(sBlo);
    int arow = warp_m + (lane & 15);
    int acol = (lane >> 4) * 8;
    unsigned aOff = (unsigned)((arow * SASTRIDE + acol) * 2);
    int brow = warp_n + (lane & 7) + ((lane >> 4) & 1) * 8;
    int bcol = ((lane >> 3) & 1) * 8;
    unsigned bHi = uBhi + (unsigned)((brow * SASTRIDE + bcol) * 2);
    unsigned bLo = uBlo + (unsigned)((brow * SASTRIDE + bcol) * 2);
    const unsigned BROW16 = 16 * SASTRIDE * 2;
    const unsigned ABUF_B = 2 * ABUF_ELEMS * 2;
    const unsigned ALO_B  = ABUF_ELEMS * 2;

    int ntiles = (nrows + BM - 1) / BM;
    int t = blockIdx.x;

    float4 pref[4];
#define LOAD_PREF(TT)                                                         \
    {                                                                         \
        _Pragma("unroll")                                                     \
        for (int i = 0; i < 4; i++) {                                         \
            int row = (TT) * BM + i * 8 + rbase;                              \
            float4 a = make_float4(0.f, 0.f, 0.f, 0.f);                       \
            if (row < nrows) {                                                \
                if (MODE == 1) {                                              \
                    float px = __ldg(&points[row * 3 + 0]);                   \
                    float py = __ldg(&points[row * 3 + 1]);                   \
                    float pz = __ldg(&points[row * 3 + 2]);                   \
                    float t0 = fmaxf(fmaf(px * w1[0] + py * w1[3] + pz * w1[6], sc1[0], sh1[0]), 0.f); \
                    float t1 = fmaxf(fmaf(px * w1[1] + py * w1[4] + pz * w1[7], sc1[1], sh1[1]), 0.f); \
                    float t2 = fmaxf(fmaf(px * w1[2] + py * w1[5] + pz * w1[8], sc1[2], sh1[2]), 0.f); \
                    a.x = fmaxf(fmaf(t0 * w20.x + t1 * w21.x + t2 * w22.x, sc4.x, sh4.x), 0.f); \
                    a.y = fmaxf(fmaf(t0 * w20.y + t1 * w21.y + t2 * w22.y, sc4.y, sh4.y), 0.f); \
                    a.z = fmaxf(fmaf(t0 * w20.z + t1 * w21.z + t2 * w22.z, sc4.z, sh4.z), 0.f); \
                    a.w = fmaxf(fmaf(t0 * w20.w + t1 * w21.w + t2 * w22.w, sc4.w, sh4.w), 0.f); \
                } else {                                                      \
                    a = __ldg((const float4*)&A[(size_t)row * CH + c]);       \
                }                                                             \
            }                                                                 \
            pref[i] = a;                                                      \
        }                                                                     \
    }
    if (t < ntiles) LOAD_PREF(t);

    int it = 0;
    while (t < ntiles) {
        int buf = it & 1;
        __nv_bfloat16* sAhi = sA + buf * 2 * ABUF_ELEMS;
        __nv_bfloat16* sAlo = sAhi + ABUF_ELEMS;
#pragma unroll
        for (int i = 0; i < 4; i++)
            store_a_split(sAhi, sAlo, i * 8 + rbase, c, pref[i]);
        __syncthreads();

        int row_lo = t * BM + warp_m + rq;
        int row_hi = row_lo + 8;
        bool ok_lo = row_lo < nrows, ok_hi = row_hi < nrows;

        float2 ext[8];
        if (MODE == 1) {
#pragma unroll
            for (int nt = 0; nt < 4; nt++) {
                int col = warp_n + nt * 8 + kq;
                ext[nt]     = ok_lo ? __ldg((const float2*)&extra[(size_t)row_lo * CH + col])
                                    : make_float2(0.f, 0.f);
                ext[4 + nt] = ok_hi ? __ldg((const float2*)&extra[(size_t)row_hi * CH + col])
                                    : make_float2(0.f, 0.f);
            }
        }
        int tn = t + GEMM_GRID;
        if (tn < ntiles) LOAD_PREF(tn);

        unsigned aHi = uA + buf * ABUF_B + aOff;
        unsigned aLo = aHi + ALO_B;
        float acc[4][4];
#pragma unroll
        for (int nt = 0; nt < 4; nt++)
#pragma unroll
            for (int j = 0; j < 4; j++) acc[nt][j] = 0.f;
#pragma unroll
        for (int ks = 0; ks < 8; ks++) {
            unsigned ko = ks * 32;
            unsigned ah[4], al[4];
            LDSM4(ah[0], ah[1], ah[2], ah[3], aHi + ko);
            LDSM4(al[0], al[1], al[2], al[3], aLo + ko);
            unsigned bh[8], bl[8];
            LDSM4(bh[0], bh[1], bh[2], bh[3], bHi + ko);
            LDSM4(bh[4], bh[5], bh[6], bh[7], bHi + BROW16 + ko);
            LDSM4(bl[0], bl[1], bl[2], bl[3], bLo + ko);
            LDSM4(bl[4], bl[5], bl[6], bl[7], bLo + BROW16 + ko);
#pragma unroll
            for (int nt = 0; nt < 4; nt++) {
                mma16816(acc[nt], ah, bh + 2 * nt);
                mma16816(acc[nt], ah, bl + 2 * nt);
                mma16816(acc[nt], al, bh + 2 * nt);
            }
        }

#pragma unroll
        for (int nt = 0; nt < 4; nt++) {
            int col = warp_n + nt * 8 + kq;
            float2 bs = *(const float2*)&bias[col];
            acc[nt][0] += bs.x; acc[nt][1] += bs.y;
            acc[nt][2] += bs.x; acc[nt][3] += bs.y;
            if (MODE == 1) {
                acc[nt][0] += ext[nt].x;     acc[nt][1] += ext[nt].y;
                acc[nt][2] += ext[4 + nt].x; acc[nt][3] += ext[4 + nt].y;
            }
            if (ok_lo)
                *(float2*)&C[(size_t)row_lo * CH + col] =
                    make_float2(acc[nt][0], acc[nt][1]);
            if (ok_hi)
                *(float2*)&C[(size_t)row_hi * CH + col] =
                    make_float2(acc[nt][2], acc[nt][3]);
        }
        t = tn; ++it;
    }
#undef LOAD_PREF
}

// ---------------- merged q+v persistent GEMM: 512 threads, 16 warps --------
// Warp grid 4(m) x 4(n); each warp: 16 rows x 32 cols of both q and v.
// Occupancy play: same smem (1 CTA/SM) but 2x warps for latency hiding.
__global__ void __launch_bounds__(QV_THREADS, 1) gemm_qv(
        const float* __restrict__ A,
        const __nv_bfloat16* __restrict__ Bqh, const __nv_bfloat16* __restrict__ Bql,
        const __nv_bfloat16* __restrict__ Bvh, const __nv_bfloat16* __restrict__ Bvl,
        const float* __restrict__ bq, const float* __restrict__ bv,
        float* __restrict__ Cq, __half* __restrict__ Cv, int nrows) {
    extern __shared__ char smraw[];
    __nv_bfloat16* sBqh = (__nv_bfloat16*)smraw;
    __nv_bfloat16* sBql = sBqh + SB_ELEMS;
    __nv_bfloat16* sBvh = sBql + SB_ELEMS;
    __nv_bfloat16* sBvl = sBvh + SB_ELEMS;
    __nv_bfloat16* sA   = sBvl + SB_ELEMS;   // [buf][hi|lo], 64 rows each

    int tid = threadIdx.x;
#pragma unroll
    for (int i = 0; i < 4; i++) {
        int g = i * QV_THREADS + tid;        // uint4 index, 2048 total
        int nn = g >> 4;
        int kk = (g & 15) * 8;
        *(uint4*)&sBqh[nn * SASTRIDE + kk] = __ldg((const uint4*)&Bqh[nn * CH + kk]);
        *(uint4*)&sBql[nn * SASTRIDE + kk] = __ldg((const uint4*)&Bql[nn * CH + kk]);
        *(uint4*)&sBvh[nn * SASTRIDE + kk] = __ldg((const uint4*)&Bvh[nn * CH + kk]);
        *(uint4*)&sBvl[nn * SASTRIDE + kk] = __ldg((const uint4*)&Bvl[nn * CH + kk]);
    }
    __syncthreads();

    int rbase = tid >> 5;                    // 0..15
    int c = (tid & 31) * 4;
    int wid = tid >> 5, lane = tid & 31;
    int warp_m = (wid & 3) * 16;
    int warp_n = (wid >> 2) * 32;
    int rq = lane >> 2;
    int kq = (lane & 3) * 2;

    unsigned uA   = (unsigned)__cvta_generic_to_shared(sA);
    unsigned uBqh = (unsigned)__cvta_generic_to_shared(sBqh);
    unsigned uBql = (unsigned)__cvta_generic_to_shared(sBql);
    unsigned uBvh = (unsigned)__cvta_generic_to_shared(sBvh);
    unsigned uBvl = (unsigned)__cvta_generic_to_shared(sBvl);
    int arow = warp_m + (lane & 15);
    int acol = (lane >> 4) * 8;
    unsigned aOff = (unsigned)((arow * SASTRIDE + acol) * 2);
    int brow = warp_n + (lane & 7) + ((lane >> 4) & 1) * 8;
    int bcol = ((lane >> 3) & 1) * 8;
    unsigned bQh = uBqh + (unsigned)((brow * SASTRIDE + bcol) * 2);
    unsigned bQl = uBql + (unsigned)((brow * SASTRIDE + bcol) * 2);
    unsigned bVh = uBvh + (unsigned)((brow * SASTRIDE + bcol) * 2);
    unsigned bVl = uBvl + (unsigned)((brow * SASTRIDE + bcol) * 2);
    const unsigned BROW16 = 16 * SASTRIDE * 2;
    const unsigned BUF_B  = 2 * ABUF64 * 2;   // bytes per double-buffer slot
    const unsigned ALO_B  = ABUF64 * 2;

    int ntiles = (nrows + QV_BM - 1) / QV_BM;
    int t = blockIdx.x;

    float4 pref[4];
#define LOAD_PREF_QV(TT)                                                      \
    {                                                                         \
        _Pragma("unroll")                                                     \
        for (int i = 0; i < 4; i++) {                                         \
            int row = (TT) * QV_BM + i * 16 + rbase;                          \
            pref[i] = (row < nrows)                                           \
                ? __ldg((const float4*)&A[(size_t)row * CH + c])              \
                : make_float4(0.f, 0.f, 0.f, 0.f);                            \
        }                                                                     \
    }
    if (t < ntiles) LOAD_PREF_QV(t);

    int it = 0;
    while (t < ntiles) {
        int buf = it & 1;
        __nv_bfloat16* sAhi = sA + buf * 2 * ABUF64;
        __nv_bfloat16* sAlo = sAhi + ABUF64;
#pragma unroll
        for (int i = 0; i < 4; i++)
            store_a_split(sAhi, sAlo, i * 16 + rbase, c, pref[i]);
        __syncthreads();

        int row_lo = t * QV_BM + warp_m + rq;
        int row_hi = row_lo + 8;
        bool ok_lo = row_lo < nrows, ok_hi = row_hi < nrows;

        int tn = t + QV_GRID;
        if (tn < ntiles) LOAD_PREF_QV(tn);

        unsigned aHi = uA + buf * BUF_B + aOff;
        unsigned aLo = aHi + ALO_B;
        float accq[4][4], accv[4][4];
#pragma unroll
        for (int nt = 0; nt < 4; nt++)
#pragma unroll
            for (int j = 0; j < 4; j++) { accq[nt][j] = 0.f; accv[nt][j] = 0.f; }
#pragma unroll
        for (int ks = 0; ks < 8; ks++) {
            unsigned ko = ks * 32;
            unsigned ah[4], al[4];
            LDSM4(ah[0], ah[1], ah[2], ah[3], aHi + ko);
            LDSM4(al[0], al[1], al[2], al[3], aLo + ko);
            unsigned qh[8], ql[8], vh[8], vl[8];
            LDSM4(qh[0], qh[1], qh[2], qh[3], bQh + ko);
            LDSM4(qh[4], qh[5], qh[6], qh[7], bQh + BROW16 + ko);
            LDSM4(ql[0], ql[1], ql[2], ql[3], bQl + ko);
            LDSM4(ql[4], ql[5], ql[6], ql[7], bQl + BROW16 + ko);
            LDSM4(vh[0], vh[1], vh[2], vh[3], bVh + ko);
            LDSM4(vh[4], vh[5], vh[6], vh[7], bVh + BROW16 + ko);
            LDSM4(vl[0], vl[1], vl[2], vl[3], bVl + ko);
            LDSM4(vl[4], vl[5], vl[6], vl[7], bVl + BROW16 + ko);
#pragma unroll
            for (int nt = 0; nt < 4; nt++) {
                mma16816(accq[nt], ah, qh + 2 * nt);
                mma16816(accq[nt], ah, ql + 2 * nt);
                mma16816(accq[nt], al, qh + 2 * nt);
                mma16816(accv[nt], ah, vh + 2 * nt);
                mma16816(accv[nt], ah, vl + 2 * nt);
                mma16816(accv[nt], al, vh + 2 * nt);
            }
        }

        // ---- q epilogue: bias + l2norm per 16ch head ----
#pragma unroll
        for (int nt = 0; nt < 4; nt++) {
            int col = warp_n + nt * 8 + kq;
            float2 bs = *(const float2*)&bq[col];
            accq[nt][0] += bs.x; accq[nt][1] += bs.y;
            accq[nt][2] += bs.x; accq[nt][3] += bs.y;
        }
#pragma unroll
        for (int hp = 0; hp < 2; hp++) {
            int n0 = hp * 2, n1 = n0 + 1;
            float s0 = accq[n0][0] * accq[n0][0] + accq[n0][1] * accq[n0][1]
                     + accq[n1][0] * accq[n1][0] + accq[n1][1] * accq[n1][1];
            float s1 = accq[n0][2] * accq[n0][2] + accq[n0][3] * accq[n0][3]
                     + accq[n1][2] * accq[n1][2] + accq[n1][3] * accq[n1][3];
            s0 += __shfl_xor_sync(0xFFFFFFFFu, s0, 1);
            s0 += __shfl_xor_sync(0xFFFFFFFFu, s0, 2);
            s1 += __shfl_xor_sync(0xFFFFFFFFu, s1, 1);
            s1 += __shfl_xor_sync(0xFFFFFFFFu, s1, 2);
            float i0 = 1.f / fmaxf(sqrtf(s0), 1e-12f);
            float i1 = 1.f / fmaxf(sqrtf(s1), 1e-12f);
            accq[n0][0] *= i0; accq[n0][1] *= i0;
            accq[n1][0] *= i0; accq[n1][1] *= i0;
            accq[n0][2] *= i1; accq[n0][3] *= i1;
            accq[n1][2] *= i1; accq[n1][3] *= i1;
        }
        // ---- v epilogue: bias + fp16 store ----
#pragma unroll
        for (int nt = 0; nt < 4; nt++) {
            int col = warp_n + nt * 8 + kq;
            float2 bs = *(const float2*)&bv[col];
            accv[nt][0] += bs.x; accv[nt][1] += bs.y;
            accv[nt][2] += bs.x; accv[nt][3] += bs.y;
            if (ok_lo) {
                *(float2*)&Cq[(size_t)row_lo * CH + col] =
                    make_float2(accq[nt][0], accq[nt][1]);
                *(__half2*)&Cv[(size_t)row_lo * CH + col] =
                    __floats2half2_rn(accv[nt][0], accv[nt][1]);
            }
            if (ok_hi) {
                *(float2*)&Cq[(size_t)row_hi * CH + col] =
                    make_float2(accq[nt][2], accq[nt][3]);
                *(__half2*)&Cv[(size_t)row_hi * CH + col] =
                    __floats2half2_rn(accv[nt][2], accv[nt][3]);
            }
        }
        t = tn; ++it;
    }
#undef LOAD_PREF_QV
}

// ---------------- 2-stage exclusive scan (scan3 folded into consumers) -----
#define SC_CHUNK 1024
__global__ void __launch_bounds__(SC_CHUNK) scan1_kernel(int n) {
    __shared__ int sm[SC_CHUNK];
    int t = threadIdx.x;
    int i = blockIdx.x * SC_CHUNK + t;
    int v = (i < n) ? g_cnt[i] : 0;
    sm[t] = v;
    __syncthreads();
#pragma unroll
    for (int o = 1; o < SC_CHUNK; o <<= 1) {
        int x = (t >= o) ? sm[t - o] : 0;
        __syncthreads();
        sm[t] += x;
        __syncthreads();
    }
    if (i < n) {
        int loc = sm[t] - v;
        g_off[i] = loc;
        g_cur[i] = loc;
    }
    if (t == SC_CHUNK - 1) g_bsum[blockIdx.x] = sm[t];
}

__global__ void __launch_bounds__(256) scan2_kernel(int nb, const float* __restrict__ pos_enc) {
    __shared__ int sm[128];
    int t = threadIdx.x;
    if (t < 128) {
        int v = (t < nb) ? g_bsum[t] : 0;
        sm[t] = v;
        __syncthreads();
#pragma unroll
        for (int o = 1; o < 128; o <<= 1) {
            int x = (t >= o) ? sm[t - o] : 0;
            __syncthreads();
            sm[t] += x;
            __syncthreads();
        }
        if (t < nb) g_bbase[t] = sm[t] - v;
    } else {
        __syncthreads();
#pragma unroll
        for (int o = 1; o < 128; o <<= 1) { __syncthreads(); __syncthreads(); }
    }
    for (int g = t; g < KVOL * 8; g += 256) {
        const float* src = pos_enc + g * 16;
        float v[16]; float s = 0.f;
#pragma unroll
        for (int i = 0; i < 16; i++) { v[i] = src[i]; s += v[i] * v[i]; }
        float inv = 1.f / fmaxf(sqrtf(s), 1e-12f);
#pragma unroll
        for (int i = 0; i < 16; i++) g_npe[g * 16 + i] = v[i] * inv;
    }
}

__global__ void __launch_bounds__(256) place_kernel(const int* __restrict__ kq, int M) {
    int i = blockIdx.x * blockDim.x + threadIdx.x;
    if (i < M) {
        int q = __ldg(&kq[M + i]);
        int pos = atomicAdd(&g_cur[q], 1) + g_bbase[q >> 10];
        int kk = __ldg(&kq[i]);
        int key = kk / KVOL;
        int kern = kk - key * KVOL;
        g_sorted[pos] = (key << 5) | kern;
    }
}

// ---------------- persistent segment gather: warp per query ----------------
#define GATHER_BLOCKS 592
__global__ void __launch_bounds__(256) gather_kernel(int n) {
    __shared__ float s_npe[KVOL * CH];
    for (int i = threadIdx.x; i < KVOL * CH / 4; i += 256)
        ((float4*)s_npe)[i] = ((const float4*)g_npe)[i];
    __syncthreads();

    int lane = threadIdx.x & 31;
    int c4 = lane * 4;
    int wid0 = (blockIdx.x * 256 + threadIdx.x) >> 5;
    const int nwarps = GATHER_BLOCKS * 8;

    for (int gw = wid0; gw < n; gw += nwarps) {
        int beg = __ldg(&g_off[gw]) + __ldg(&g_bbase[gw >> 10]);
        int cnt = __ldg(&g_cnt[gw]);
        float4 qv = __ldcs((const float4*)&g_q[(size_t)gw * CH + c4]);
        float4 acc = make_float4(0.f, 0.f, 0.f, 0.f);

        int i = 0;
        for (; i + 8 <= cnt; i += 8) {
            int e[8];
#pragma unroll
            for (int j = 0; j < 8; j++) e[j] = __ldg(&g_sorted[beg + i + j]);
            uint2 vh[8];
#pragma unroll
            for (int j = 0; j < 8; j++)
                vh[j] = __ldg((const uint2*)&g_vh[(size_t)(e[j] >> 5) * CH + c4]);
            float s[8];
#pragma unroll
            for (int j = 0; j < 8; j++) {
                float4 p = *(const float4*)&s_npe[(e[j] & 31) * CH + c4];
                float t = qv.x * p.x + qv.y * p.y + qv.z * p.z + qv.w * p.w;
                t += __shfl_xor_sync(0xFFFFFFFFu, t, 1);
                t += __shfl_xor_sync(0xFFFFFFFFu, t, 2);
                s[j] = t;
            }
#pragma unroll
            for (int j = 0; j < 8; j++) {
                float2 v0 = __half22float2(*(const __half2*)&vh[j].x);
                float2 v1 = __half22float2(*(const __half2*)&vh[j].y);
                acc.x = fmaf(s[j], v0.x, acc.x);
                acc.y = fmaf(s[j], v0.y, acc.y);
                acc.z = fmaf(s[j], v1.x, acc.z);
                acc.w = fmaf(s[j], v1.y, acc.w);
            }
        }
        if (i + 4 <= cnt) {
            int e[4];
#pragma unroll
            for (int j = 0; j < 4; j++) e[j] = __ldg(&g_sorted[beg + i + j]);
            uint2 vh[4];
#pragma unroll
            for (int j = 0; j < 4; j++)
                vh[j] = __ldg((const uint2*)&g_vh[(size_t)(e[j] >> 5) * CH + c4]);
#pragma unroll
            for (int j = 0; j < 4; j++) {
                float4 p = *(const float4*)&s_npe[(e[j] & 31) * CH + c4];
                float t = qv.x * p.x + qv.y * p.y + qv.z * p.z + qv.w * p.w;
                t += __shfl_xor_sync(0xFFFFFFFFu, t, 1);
                t += __shfl_xor_sync(0xFFFFFFFFu, t, 2);
                float2 v0 = __half22float2(*(const __half2*)&vh[j].x);
                float2 v1 = __half22float2(*(const __half2*)&vh[j].y);
                acc.x = fmaf(t, v0.x, acc.x);
                acc.y = fmaf(t, v0.y, acc.y);
                acc.z = fmaf(t, v1.x, acc.z);
                acc.w = fmaf(t, v1.y, acc.w);
            }
            i += 4;
        }
        for (; i < cnt; i++) {
            int e = __ldg(&g_sorted[beg + i]);
            uint2 vh = __ldg((const uint2*)&g_vh[(size_t)(e >> 5) * CH + c4]);
            float4 p = *(const float4*)&s_npe[(e & 31) * CH + c4];
            float t = qv.x * p.x + qv.y * p.y + qv.z * p.z + qv.w * p.w;
            t += __shfl_xor_sync(0xFFFFFFFFu, t, 1);
            t += __shfl_xor_sync(0xFFFFFFFFu, t, 2);
            float2 v0 = __half22float2(*(const __half2*)&vh.x);
            float2 v1 = __half22float2(*(const __half2*)&vh.y);
            acc.x = fmaf(t, v0.x, acc.x);
            acc.y = fmaf(t, v0.y, acc.y);
            acc.z = fmaf(t, v1.x, acc.z);
            acc.w = fmaf(t, v1.y, acc.w);
        }
        *(float4*)&g_acc[(size_t)gw * CH + c4] = acc;
    }
}

// ---------------- host launch ----------------------------------------------
extern "C" void kernel_launch(void* const* d_in, const int* in_sizes, int n_in,
                              void* d_out, int out_size) {
    const float* feats   = (const float*)d_in[0];
    const float* points  = (const float*)d_in[1];
    const int*   kq      = (const int*)d_in[2];
    const float* W1 = (const float*)d_in[3];
    const float* g1 = (const float*)d_in[4];
    const float* b1 = (const float*)d_in[5];
    const float* W2 = (const float*)d_in[6];
    const float* g2 = (const float*)d_in[7];
    const float* b2 = (const float*)d_in[8];
    const float* W3 = (const float*)d_in[9];
    const float* b3 = (const float*)d_in[10];
    const float* Wq = (const float*)d_in[11];
    const float* bq = (const float*)d_in[12];
    const float* Wv = (const float*)d_in[13];
    const float* bv = (const float*)d_in[14];
    const float* pos_enc = (const float*)d_in[15];
    const float* Wo = (const float*)d_in[16];
    const float* bo = (const float*)d_in[17];

    int N = in_sizes[0] / CH;
    int M = in_sizes[2] / 2;

    cudaFuncSetAttribute((const void*)gemm_p<0>,
                         cudaFuncAttributeMaxDynamicSharedMemorySize, TC_SMEM_1);
    cudaFuncSetAttribute((const void*)gemm_p<1>,
                         cudaFuncAttributeMaxDynamicSharedMemorySize, TC_SMEM_1);
    cudaFuncSetAttribute((const void*)gemm_qv,
                         cudaFuncAttributeMaxDynamicSharedMemorySize, TC_SMEM_QV);

    float* xp; float* qp; float* ap; __half* vhp;
    __nv_bfloat16* whi; __nv_bfloat16* wlo;
    { void* t; cudaGetSymbolAddress(&t, g_x);   xp  = (float*)t; }
    { void* t; cudaGetSymbolAddress(&t, g_q);   qp  = (float*)t; }
    { void* t; cudaGetSymbolAddress(&t, g_vh);  vhp = (__half*)t; }
    { void* t; cudaGetSymbolAddress(&t, g_acc); ap  = (float*)t; }
    { void* t; cudaGetSymbolAddress(&t, g_Whi); whi = (__nv_bfloat16*)t; }
    { void* t; cudaGetSymbolAddress(&t, g_Wlo); wlo = (__nv_bfloat16*)t; }
    void* cntp = nullptr; void* s1p = nullptr; void* s2p = nullptr;
    cudaGetSymbolAddress(&cntp, g_cnt);
    cudaGetSymbolAddress(&s1p, g_s1);
    cudaGetSymbolAddress(&s2p, g_s2);
    cudaMemsetAsync(cntp, 0, (size_t)N * sizeof(int), 0);
    cudaMemsetAsync(s1p, 0, 8 * sizeof(float), 0);
    cudaMemsetAsync(s2p, 0, 2 * CH * sizeof(float), 0);

    int nsb = (N + SC_CHUNK - 1) / SC_CHUNK;

    stats1_kernel<<<256, 256>>>(points, W1, N, W3, Wq, Wv, Wo, kq, M);
    h2_kernel<<<(N + H2_PB - 1) / H2_PB, 256>>>(points, W1, g1, b1, W2, N);

    // x = relu(bn2(h2(points))) @ W3 + b3 + feats
    gemm_p<1><<<GEMM_GRID, 256, TC_SMEM_1>>>(nullptr, whi + 0 * CH * CH, wlo + 0 * CH * CH,
                                             b3, xp, feats, g2, b2, points, W1, W2, N);
    // q (l2norm, fp32) and v (fp16) in one pass over x, 512 threads/CTA
    gemm_qv<<<QV_GRID, QV_THREADS, TC_SMEM_QV>>>(xp,
                                          whi + 1 * CH * CH, wlo + 1 * CH * CH,
                                          whi + 2 * CH * CH, wlo + 2 * CH * CH,
                                          bq, bv, qp, vhp, N);

    // counting sort
    scan1_kernel<<<nsb, SC_CHUNK>>>(N);
    scan2_kernel<<<1, 256>>>(nsb, pos_enc);
    place_kernel<<<(M + 255) / 256, 256>>>(kq, M);

    // attention: persistent segment gather
    gather_kernel<<<GATHER_BLOCKS, 256>>>(N);

    // out = acc @ Wo + bo
    gemm_p<0><<<GEMM_GRID, 256, TC_SMEM_1>>>(ap, whi + 3 * CH * CH, wlo + 3 * CH * CH,
                                             bo, (float*)d_out, nullptr, nullptr, nullptr,
                                             nullptr, nullptr, nullptr, N);
}